// round 2
// baseline (speedup 1.0000x reference)
#include <cuda_runtime.h>

// BlockDiagAttention: B=4,H=16,N=4128,D=64. 64x64 diagonal attention blocks
// (+ one 32-row remainder block per head). fp32 in/out.
// R2: 8x8 register blocking (64 threads/tile) -> 1 B/MAC smem traffic (was 2),
//     softmax in registers via shfl over the 8-lane tx group.
#define NSEQ   4128
#define TILES  65
#define STRIDE 66   // 64 + 2 pad floats

__device__ __forceinline__ unsigned long long ffma2(unsigned long long a,
                                                    unsigned long long b,
                                                    unsigned long long c) {
    unsigned long long d;
    asm("fma.rn.f32x2 %0, %1, %2, %3;" : "=l"(d) : "l"(a), "l"(b), "l"(c));
    return d;
}

__device__ __forceinline__ float2 unpack2(unsigned long long a) {
    float2 f;
    asm("mov.b64 {%0, %1}, %2;" : "=f"(f.x), "=f"(f.y) : "l"(a));
    return f;
}

extern __shared__ float smem_dyn[];

__global__ __launch_bounds__(64)
void bd_attn_kernel(const float* __restrict__ q, const float* __restrict__ k,
                    const float* __restrict__ v, float* __restrict__ out)
{
    float* smQ  = smem_dyn;                   // Q tile; later reused as P
    float* smK  = smem_dyn + 64 * STRIDE;     // K tile
    float* smVt = smem_dyn + 2 * 64 * STRIDE; // V tile transposed: Vt[d][m]

    const int tid  = threadIdx.x;
    const int bh   = blockIdx.x / TILES;
    const int t    = blockIdx.x % TILES;
    const int row0 = t * 64;
    const int nrows = min(64, NSEQ - row0);   // 64 or 32 (remainder)

    const size_t base = ((size_t)bh * NSEQ + row0) * 64;
    const float* qb = q + base;
    const float* kb = k + base;
    const float* vb = v + base;

    // ---- Load Q,K row-major (padded) and V transposed. Zero-fill beyond nrows.
    for (int i = tid; i < 64 * 16; i += 64) {
        int r = i >> 4;
        int c = (i & 15) << 2;
        float4 zq = make_float4(0.f, 0.f, 0.f, 0.f);
        float4 zk = zq, zv = zq;
        if (r < nrows) {
            zq = *(const float4*)(qb + r * 64 + c);
            zk = *(const float4*)(kb + r * 64 + c);
            zv = *(const float4*)(vb + r * 64 + c);
        }
        float* dq = &smQ[r * STRIDE + c];
        *(float2*)(dq)     = make_float2(zq.x, zq.y);
        *(float2*)(dq + 2) = make_float2(zq.z, zq.w);
        float* dk = &smK[r * STRIDE + c];
        *(float2*)(dk)     = make_float2(zk.x, zk.y);
        *(float2*)(dk + 2) = make_float2(zk.z, zk.w);
        smVt[(c + 0) * STRIDE + r] = zv.x;
        smVt[(c + 1) * STRIDE + r] = zv.y;
        smVt[(c + 2) * STRIDE + r] = zv.z;
        smVt[(c + 3) * STRIDE + r] = zv.w;
    }
    __syncthreads();

    const int tx = tid & 7;    // col group: owns cols tx + 8c
    const int ty = tid >> 3;   // row group: owns rows ty + 8r

    // ---- S = Q K^T  (packed f32x2 along d), 8x8 register tile
    unsigned long long acc[8][8];
#pragma unroll
    for (int r = 0; r < 8; ++r)
#pragma unroll
        for (int c = 0; c < 8; ++c) acc[r][c] = 0ull;

#pragma unroll 1
    for (int dd = 0; dd < 32; ++dd) {
        unsigned long long q2[8], k2[8];
#pragma unroll
        for (int r = 0; r < 8; ++r)
            q2[r] = *(const unsigned long long*)&smQ[(ty + 8 * r) * STRIDE + 2 * dd];
#pragma unroll
        for (int c = 0; c < 8; ++c)
            k2[c] = *(const unsigned long long*)&smK[(tx + 8 * c) * STRIDE + 2 * dd];
#pragma unroll
        for (int r = 0; r < 8; ++r)
#pragma unroll
            for (int c = 0; c < 8; ++c)
                acc[r][c] = ffma2(q2[r], k2[c], acc[r][c]);
    }

    // ---- softmax entirely in registers (rows owned within the tx group of 8 lanes)
    float p[8][8];
#pragma unroll
    for (int r = 0; r < 8; ++r) {
        float s[8];
        float m = -1e30f;
#pragma unroll
        for (int c = 0; c < 8; ++c) {
            float2 f = unpack2(acc[r][c]);
            float val = (f.x + f.y) * 0.125f;
            s[c] = (tx + 8 * c < nrows) ? val : -1e30f;
            m = fmaxf(m, s[c]);
        }
#pragma unroll
        for (int o = 1; o < 8; o <<= 1)
            m = fmaxf(m, __shfl_xor_sync(0xffffffffu, m, o));
        float sum = 0.f;
#pragma unroll
        for (int c = 0; c < 8; ++c) {
            s[c] = __expf(s[c] - m);
            sum += s[c];
        }
#pragma unroll
        for (int o = 1; o < 8; o <<= 1)
            sum += __shfl_xor_sync(0xffffffffu, sum, o);
        float inv = __frcp_rn(sum);
#pragma unroll
        for (int c = 0; c < 8; ++c) p[r][c] = s[c] * inv;
    }

    __syncthreads();   // all GEMM1 smem reads done; smQ becomes P buffer

#pragma unroll
    for (int r = 0; r < 8; ++r)
#pragma unroll
        for (int c = 0; c < 8; ++c)
            smQ[(ty + 8 * r) * STRIDE + (tx + 8 * c)] = p[r][c];
    __syncthreads();

    // ---- O = P V  (packed f32x2 along m, V transposed in smem)
#pragma unroll
    for (int r = 0; r < 8; ++r)
#pragma unroll
        for (int c = 0; c < 8; ++c) acc[r][c] = 0ull;

#pragma unroll 1
    for (int mm = 0; mm < 32; ++mm) {
        unsigned long long p2[8], v2[8];
#pragma unroll
        for (int r = 0; r < 8; ++r)
            p2[r] = *(const unsigned long long*)&smQ[(ty + 8 * r) * STRIDE + 2 * mm];
#pragma unroll
        for (int c = 0; c < 8; ++c)
            v2[c] = *(const unsigned long long*)&smVt[(tx + 8 * c) * STRIDE + 2 * mm];
#pragma unroll
        for (int r = 0; r < 8; ++r)
#pragma unroll
            for (int c = 0; c < 8; ++c)
                acc[r][c] = ffma2(p2[r], v2[c], acc[r][c]);
    }

    float* ob = out + base;
#pragma unroll
    for (int r = 0; r < 8; ++r) {
        int i = ty + 8 * r;
        if (i < nrows) {
#pragma unroll
            for (int c = 0; c < 8; ++c) {
                float2 f = unpack2(acc[r][c]);
                ob[i * 64 + (tx + 8 * c)] = f.x + f.y;
            }
        }
    }
}

extern "C" void kernel_launch(void* const* d_in, const int* in_sizes, int n_in,
                              void* d_out, int out_size) {
    const float* q = (const float*)d_in[0];
    const float* k = (const float*)d_in[1];
    const float* v = (const float*)d_in[2];
    float* out = (float*)d_out;

    const int bh = in_sizes[0] / (NSEQ * 64);      // B*H = 64
    const int smem_bytes = 3 * 64 * STRIDE * (int)sizeof(float);  // 50688

    cudaFuncSetAttribute(bd_attn_kernel,
                         cudaFuncAttributeMaxDynamicSharedMemorySize, smem_bytes);
    bd_attn_kernel<<<bh * TILES, 64, smem_bytes>>>(q, k, v, out);
}

// round 3
// speedup vs baseline: 1.0955x; 1.0955x over previous
#include <cuda_runtime.h>

// BlockDiagAttention: B=4,H=16,N=4128,D=64. fp32.
// R3: 8x8 register blocking, 64 thr/tile, smem cut to 2 buffers (K->Vt reuse,
//     Q->P reuse) = 33.8KB -> 6 CTAs/SM (12 warps). V prefetched to L2 early,
//     loaded to smem after GEMM1. Permuted m-layout makes P stores vectorized.
#define NSEQ   4128
#define TILES  65
#define STRIDE 66

__device__ __forceinline__ unsigned long long ffma2(unsigned long long a,
                                                    unsigned long long b,
                                                    unsigned long long c) {
    unsigned long long d;
    asm("fma.rn.f32x2 %0, %1, %2, %3;" : "=l"(d) : "l"(a), "l"(b), "l"(c));
    return d;
}

__device__ __forceinline__ float2 unpack2(unsigned long long a) {
    float2 f;
    asm("mov.b64 {%0, %1}, %2;" : "=f"(f.x), "=f"(f.y) : "l"(a));
    return f;
}

extern __shared__ float smem_dyn[];

__global__ __launch_bounds__(64, 6)
void bd_attn_kernel(const float* __restrict__ q, const float* __restrict__ k,
                    const float* __restrict__ v, float* __restrict__ out)
{
    float* smA = smem_dyn;                // Q tile, later P (permuted cols)
    float* smB = smem_dyn + 64 * STRIDE;  // K tile, later Vt (permuted cols)

    const int tid  = threadIdx.x;
    const int bh   = blockIdx.x / TILES;
    const int t    = blockIdx.x % TILES;
    const int row0 = t * 64;
    const int nrows = min(64, NSEQ - row0);   // 64 or 32

    const size_t base = ((size_t)bh * NSEQ + row0) * 64;
    const float* qb = q + base;
    const float* kb = k + base;
    const float* vb = v + base;

    // ---- Prefetch V tile into L2 (consumed after GEMM1). 16KB = 128 lines.
    {
        const char* vp = (const char*)vb;
        int lines = (nrows * 64 * 4) >> 7;       // 128 or 64
        for (int l = tid; l < lines; l += 64)
            asm volatile("prefetch.global.L2 [%0];" :: "l"(vp + (size_t)l * 128));
    }

    // ---- Load Q -> smA, K -> smB (row-major, padded). Zero-fill beyond nrows.
    for (int i = tid; i < 64 * 16; i += 64) {
        int r = i >> 4;
        int c = (i & 15) << 2;
        float4 zq = make_float4(0.f, 0.f, 0.f, 0.f);
        float4 zk = zq;
        if (r < nrows) {
            zq = *(const float4*)(qb + r * 64 + c);
            zk = *(const float4*)(kb + r * 64 + c);
        }
        float* dq = &smA[r * STRIDE + c];
        *(float2*)(dq)     = make_float2(zq.x, zq.y);
        *(float2*)(dq + 2) = make_float2(zq.z, zq.w);
        float* dk = &smB[r * STRIDE + c];
        *(float2*)(dk)     = make_float2(zk.x, zk.y);
        *(float2*)(dk + 2) = make_float2(zk.z, zk.w);
    }
    __syncthreads();

    const int tx = tid & 7;    // owns cols tx + 8c
    const int ty = tid >> 3;   // owns rows ty + 8r

    // ---- S = Q K^T  (packed f32x2 along d)
    unsigned long long acc[8][8];
#pragma unroll
    for (int r = 0; r < 8; ++r)
#pragma unroll
        for (int c = 0; c < 8; ++c) acc[r][c] = 0ull;

#pragma unroll 1
    for (int dd = 0; dd < 32; ++dd) {
        unsigned long long q2[8], k2[8];
#pragma unroll
        for (int r = 0; r < 8; ++r)
            q2[r] = *(const unsigned long long*)&smA[(ty + 8 * r) * STRIDE + 2 * dd];
#pragma unroll
        for (int c = 0; c < 8; ++c)
            k2[c] = *(const unsigned long long*)&smB[(tx + 8 * c) * STRIDE + 2 * dd];
#pragma unroll
        for (int r = 0; r < 8; ++r)
#pragma unroll
            for (int c = 0; c < 8; ++c)
                acc[r][c] = ffma2(q2[r], k2[c], acc[r][c]);
    }

    // ---- softmax in registers (row groups of 8 lanes share via shfl)
    float p[8][8];
#pragma unroll
    for (int r = 0; r < 8; ++r) {
        float s[8];
        float m = -1e30f;
#pragma unroll
        for (int c = 0; c < 8; ++c) {
            float2 f = unpack2(acc[r][c]);
            float val = (f.x + f.y) * 0.125f;
            s[c] = (tx + 8 * c < nrows) ? val : -1e30f;
            m = fmaxf(m, s[c]);
        }
#pragma unroll
        for (int o = 1; o < 8; o <<= 1)
            m = fmaxf(m, __shfl_xor_sync(0xffffffffu, m, o));
        float sum = 0.f;
#pragma unroll
        for (int c = 0; c < 8; ++c) {
            s[c] = __expf(s[c] - m);
            sum += s[c];
        }
#pragma unroll
        for (int o = 1; o < 8; o <<= 1)
            sum += __shfl_xor_sync(0xffffffffu, sum, o);
        float inv = __frcp_rn(sum);
#pragma unroll
        for (int c = 0; c < 8; ++c) p[r][c] = s[c] * inv;
    }

    __syncthreads();   // GEMM1 reads done: smA free for P, smB free for Vt

    // ---- store P with permuted m-index: col' = tx*8 + c (contiguous -> STS.64)
#pragma unroll
    for (int r = 0; r < 8; ++r) {
        float* dst = &smA[(ty + 8 * r) * STRIDE + tx * 8];
#pragma unroll
        for (int c = 0; c < 8; c += 2)
            *(float2*)(dst + c) = make_float2(p[r][c], p[r][c + 1]);
    }

    // ---- load V -> smB transposed with SAME m-permutation: Vt[d][perm(m)]
    for (int i = tid; i < 64 * 16; i += 64) {
        int r = i >> 4;                 // m index
        int c = (i & 15) << 2;          // d index
        float4 zv = make_float4(0.f, 0.f, 0.f, 0.f);
        if (r < nrows) zv = *(const float4*)(vb + r * 64 + c);
        int pr = ((r & 7) << 3) | (r >> 3);   // perm(m)
        smB[(c + 0) * STRIDE + pr] = zv.x;
        smB[(c + 1) * STRIDE + pr] = zv.y;
        smB[(c + 2) * STRIDE + pr] = zv.z;
        smB[(c + 3) * STRIDE + pr] = zv.w;
    }
    __syncthreads();

    // ---- O = P V  (packed f32x2 along permuted m; permutation cancels)
#pragma unroll
    for (int r = 0; r < 8; ++r)
#pragma unroll
        for (int c = 0; c < 8; ++c) acc[r][c] = 0ull;

#pragma unroll 1
    for (int mm = 0; mm < 32; ++mm) {
        unsigned long long p2[8], v2[8];
#pragma unroll
        for (int r = 0; r < 8; ++r)
            p2[r] = *(const unsigned long long*)&smA[(ty + 8 * r) * STRIDE + 2 * mm];
#pragma unroll
        for (int c = 0; c < 8; ++c)
            v2[c] = *(const unsigned long long*)&smB[(tx + 8 * c) * STRIDE + 2 * mm];
#pragma unroll
        for (int r = 0; r < 8; ++r)
#pragma unroll
            for (int c = 0; c < 8; ++c)
                acc[r][c] = ffma2(p2[r], v2[c], acc[r][c]);
    }

    float* ob = out + base;
#pragma unroll
    for (int r = 0; r < 8; ++r) {
        int i = ty + 8 * r;
        if (i < nrows) {
#pragma unroll
            for (int c = 0; c < 8; ++c) {
                float2 f = unpack2(acc[r][c]);
                ob[i * 64 + (tx + 8 * c)] = f.x + f.y;
            }
        }
    }
}

extern "C" void kernel_launch(void* const* d_in, const int* in_sizes, int n_in,
                              void* d_out, int out_size) {
    const float* q = (const float*)d_in[0];
    const float* k = (const float*)d_in[1];
    const float* v = (const float*)d_in[2];
    float* out = (float*)d_out;

    const int bh = in_sizes[0] / (NSEQ * 64);                      // 64
    const int smem_bytes = 2 * 64 * STRIDE * (int)sizeof(float);   // 33792

    cudaFuncSetAttribute(bd_attn_kernel,
                         cudaFuncAttributeMaxDynamicSharedMemorySize, smem_bytes);
    bd_attn_kernel<<<bh * TILES, 64, smem_bytes>>>(q, k, v, out);
}

// round 4
// speedup vs baseline: 2.1588x; 1.9706x over previous
#include <cuda_runtime.h>
#include <cuda_bf16.h>

// BlockDiagAttention: B=4,H=16,N=4128,D=64. fp32 in/out.
// R4: tensor-core path. fp32 -> (bf16_hi, bf16_lo) split; S = QhKh + QhKl + QlKh
// via mma.sync.m16n8k16 (rel err ~1e-5). Softmax + P-split fully in registers
// (GEMM1 C-layout == GEMM2 A-layout). 4 warps/tile, 128 thr.
#define NSEQ  4128
#define TILES 65
#define QSTR  36   // row stride in u32 units (72 bf16 = 144 B), conflict-free

__device__ __forceinline__ void mma16816(float c[4], const unsigned a[4],
                                         const unsigned b[2]) {
    asm volatile(
        "mma.sync.aligned.m16n8k16.row.col.f32.bf16.bf16.f32 "
        "{%0,%1,%2,%3}, {%4,%5,%6,%7}, {%8,%9}, {%0,%1,%2,%3};"
        : "+f"(c[0]), "+f"(c[1]), "+f"(c[2]), "+f"(c[3])
        : "r"(a[0]), "r"(a[1]), "r"(a[2]), "r"(a[3]), "r"(b[0]), "r"(b[1]));
}

// pack (x0,x1) -> bf16x2 hi + bf16x2 lo (residual)
__device__ __forceinline__ void split2(float x0, float x1, unsigned& h, unsigned& l) {
    __nv_bfloat162 hh = __floats2bfloat162_rn(x0, x1);   // .x = x0 (low half)
    float r0 = x0 - __bfloat162float(hh.x);
    float r1 = x1 - __bfloat162float(hh.y);
    __nv_bfloat162 ll = __floats2bfloat162_rn(r0, r1);
    h = *(unsigned*)&hh;
    l = *(unsigned*)&ll;
}

extern __shared__ unsigned smem_u32[];

__global__ __launch_bounds__(128, 4)
void bd_attn_kernel(const float* __restrict__ q, const float* __restrict__ k,
                    const float* __restrict__ v, float* __restrict__ out)
{
    unsigned* sQh = smem_u32;              // later: Vt hi
    unsigned* sQl = smem_u32 + 64 * QSTR;  // later: Vt lo
    unsigned* sKh = smem_u32 + 2 * 64 * QSTR;
    unsigned* sKl = smem_u32 + 3 * 64 * QSTR;

    const int tid  = threadIdx.x;
    const int bh   = blockIdx.x / TILES;
    const int t_   = blockIdx.x % TILES;
    const int row0 = t_ * 64;
    const int nrows = min(64, NSEQ - row0);   // 64 or 32

    const size_t base = ((size_t)bh * NSEQ + row0) * 64;
    const float* qb = q + base;
    const float* kb = k + base;
    const float* vb = v + base;

    // ---- L2 prefetch of V (consumed after GEMM1)
    {
        const char* vp = (const char*)vb;
        int lines = (nrows * 64 * 4) >> 7;
        for (int l = tid; l < lines; l += 128)
            asm volatile("prefetch.global.L2 [%0];" :: "l"(vp + (size_t)l * 128));
    }

    // ---- Load Q,K -> smem split bf16 (coalesced: 8 lanes cover one row)
#pragma unroll
    for (int p = 0; p < 4; ++p) {
        int i  = tid + 128 * p;
        int r  = i >> 3;
        int c8 = (i & 7) << 3;
        float4 f0 = make_float4(0.f,0.f,0.f,0.f), f1 = f0;
        float4 g0 = f0, g1 = f0;
        if (r < nrows) {
            f0 = *(const float4*)(qb + r * 64 + c8);
            f1 = *(const float4*)(qb + r * 64 + c8 + 4);
            g0 = *(const float4*)(kb + r * 64 + c8);
            g1 = *(const float4*)(kb + r * 64 + c8 + 4);
        }
        unsigned h[4], l[4];
        split2(f0.x, f0.y, h[0], l[0]); split2(f0.z, f0.w, h[1], l[1]);
        split2(f1.x, f1.y, h[2], l[2]); split2(f1.z, f1.w, h[3], l[3]);
        *(uint4*)&sQh[r * QSTR + (c8 >> 1)] = make_uint4(h[0],h[1],h[2],h[3]);
        *(uint4*)&sQl[r * QSTR + (c8 >> 1)] = make_uint4(l[0],l[1],l[2],l[3]);
        split2(g0.x, g0.y, h[0], l[0]); split2(g0.z, g0.w, h[1], l[1]);
        split2(g1.x, g1.y, h[2], l[2]); split2(g1.z, g1.w, h[3], l[3]);
        *(uint4*)&sKh[r * QSTR + (c8 >> 1)] = make_uint4(h[0],h[1],h[2],h[3]);
        *(uint4*)&sKl[r * QSTR + (c8 >> 1)] = make_uint4(l[0],l[1],l[2],l[3]);
    }
    __syncthreads();

    const int lane = tid & 31;
    const int w    = tid >> 5;      // warp: rows 16w..16w+15
    const int g    = lane >> 2;
    const int t    = lane & 3;

    // ---- GEMM1: S = Q K^T (3 split products per mma chunk)
    float S[8][4];
#pragma unroll
    for (int ch = 0; ch < 8; ++ch)
#pragma unroll
        for (int j = 0; j < 4; ++j) S[ch][j] = 0.f;

#pragma unroll
    for (int kk = 0; kk < 4; ++kk) {
        const int abase = (16 * w + g) * QSTR + 8 * kk + t;
        unsigned aH[4], aL[4];
        aH[0] = sQh[abase];           aH[1] = sQh[abase + 8 * QSTR];
        aH[2] = sQh[abase + 4];       aH[3] = sQh[abase + 8 * QSTR + 4];
        aL[0] = sQl[abase];           aL[1] = sQl[abase + 8 * QSTR];
        aL[2] = sQl[abase + 4];       aL[3] = sQl[abase + 8 * QSTR + 4];
#pragma unroll
        for (int ch = 0; ch < 8; ++ch) {
            const int bbase = (8 * ch + g) * QSTR + 8 * kk + t;
            unsigned bH[2] = { sKh[bbase], sKh[bbase + 4] };
            unsigned bL[2] = { sKl[bbase], sKl[bbase + 4] };
            mma16816(S[ch], aH, bH);
            mma16816(S[ch], aH, bL);
            mma16816(S[ch], aL, bH);
        }
    }

    // ---- softmax in registers. Thread holds rows g (j=0,1), g+8 (j=2,3);
    //      cols 8ch+2t+(j&1).
    float mx0 = -1e30f, mx1 = -1e30f;
#pragma unroll
    for (int ch = 0; ch < 8; ++ch) {
#pragma unroll
        for (int j = 0; j < 4; ++j) {
            int col = 8 * ch + 2 * t + (j & 1);
            S[ch][j] = (col < nrows) ? S[ch][j] * 0.125f : -1e30f;
        }
        mx0 = fmaxf(mx0, fmaxf(S[ch][0], S[ch][1]));
        mx1 = fmaxf(mx1, fmaxf(S[ch][2], S[ch][3]));
    }
    mx0 = fmaxf(mx0, __shfl_xor_sync(0xffffffffu, mx0, 1));
    mx0 = fmaxf(mx0, __shfl_xor_sync(0xffffffffu, mx0, 2));
    mx1 = fmaxf(mx1, __shfl_xor_sync(0xffffffffu, mx1, 1));
    mx1 = fmaxf(mx1, __shfl_xor_sync(0xffffffffu, mx1, 2));

    float sum0 = 0.f, sum1 = 0.f;
#pragma unroll
    for (int ch = 0; ch < 8; ++ch) {
        S[ch][0] = __expf(S[ch][0] - mx0);
        S[ch][1] = __expf(S[ch][1] - mx0);
        S[ch][2] = __expf(S[ch][2] - mx1);
        S[ch][3] = __expf(S[ch][3] - mx1);
        sum0 += S[ch][0] + S[ch][1];
        sum1 += S[ch][2] + S[ch][3];
    }
    sum0 += __shfl_xor_sync(0xffffffffu, sum0, 1);
    sum0 += __shfl_xor_sync(0xffffffffu, sum0, 2);
    sum1 += __shfl_xor_sync(0xffffffffu, sum1, 1);
    sum1 += __shfl_xor_sync(0xffffffffu, sum1, 2);
    const float inv0 = __frcp_rn(sum0);
    const float inv1 = __frcp_rn(sum1);

    // ---- P fragments (bf16 hi/lo) straight from accumulators.
    // GEMM2 A chunk kk needs cols 16kk+{2t,2t+1} (a0/a1) and +8 (a2/a3):
    // those are S chunks 2kk and 2kk+1.
    unsigned pH[4][4], pL[4][4];
#pragma unroll
    for (int kk = 0; kk < 4; ++kk) {
        split2(S[2*kk][0]   * inv0, S[2*kk][1]   * inv0, pH[kk][0], pL[kk][0]);
        split2(S[2*kk][2]   * inv1, S[2*kk][3]   * inv1, pH[kk][1], pL[kk][1]);
        split2(S[2*kk+1][0] * inv0, S[2*kk+1][1] * inv0, pH[kk][2], pL[kk][2]);
        split2(S[2*kk+1][2] * inv1, S[2*kk+1][3] * inv1, pH[kk][3], pL[kk][3]);
    }

    __syncthreads();   // all GEMM1 smem reads done; sQh/sQl become Vt hi/lo

    // ---- Load V -> smem transposed split bf16: Vt[d][m]
    {
        __nv_bfloat16* vh = (__nv_bfloat16*)sQh;
        __nv_bfloat16* vl = (__nv_bfloat16*)sQl;
#pragma unroll
        for (int p = 0; p < 4; ++p) {
            int i  = tid + 128 * p;
            int r  = i & 63;            // m index (lane-consecutive for STS)
            int c8 = (i >> 6) << 3;     // d chunk
            float4 f0 = make_float4(0.f,0.f,0.f,0.f), f1 = f0;
            if (r < nrows) {
                f0 = *(const float4*)(vb + r * 64 + c8);
                f1 = *(const float4*)(vb + r * 64 + c8 + 4);
            }
            float xs[8] = { f0.x, f0.y, f0.z, f0.w, f1.x, f1.y, f1.z, f1.w };
#pragma unroll
            for (int j = 0; j < 8; ++j) {
                __nv_bfloat16 hb = __float2bfloat16_rn(xs[j]);
                __nv_bfloat16 lb = __float2bfloat16_rn(xs[j] - __bfloat162float(hb));
                vh[(c8 + j) * (2 * QSTR) + r] = hb;
                vl[(c8 + j) * (2 * QSTR) + r] = lb;
            }
        }
    }
    __syncthreads();

    // ---- GEMM2: O = P V  (B frags from Vt, pairs along m contiguous)
    float O[8][4];
#pragma unroll
    for (int ch = 0; ch < 8; ++ch)
#pragma unroll
        for (int j = 0; j < 4; ++j) O[ch][j] = 0.f;

#pragma unroll
    for (int kk = 0; kk < 4; ++kk) {
#pragma unroll
        for (int ch = 0; ch < 8; ++ch) {
            const int bbase = (8 * ch + g) * QSTR + 8 * kk + t;
            unsigned bH[2] = { sQh[bbase], sQh[bbase + 4] };
            unsigned bL[2] = { sQl[bbase], sQl[bbase + 4] };
            mma16816(O[ch], pH[kk], bH);
            mma16816(O[ch], pH[kk], bL);
            mma16816(O[ch], pL[kk], bH);
        }
    }

    // ---- write O
    float* ob = out + base;
    const int r0 = 16 * w + g;
    const int r1 = r0 + 8;
#pragma unroll
    for (int ch = 0; ch < 8; ++ch) {
        int col = 8 * ch + 2 * t;
        if (r0 < nrows)
            *(float2*)(ob + r0 * 64 + col) = make_float2(O[ch][0], O[ch][1]);
        if (r1 < nrows)
            *(float2*)(ob + r1 * 64 + col) = make_float2(O[ch][2], O[ch][3]);
    }
}

extern "C" void kernel_launch(void* const* d_in, const int* in_sizes, int n_in,
                              void* d_out, int out_size) {
    const float* q = (const float*)d_in[0];
    const float* k = (const float*)d_in[1];
    const float* v = (const float*)d_in[2];
    float* out = (float*)d_out;

    const int bh = in_sizes[0] / (NSEQ * 64);                  // 64
    const int smem_bytes = 4 * 64 * QSTR * (int)sizeof(unsigned);  // 36864

    cudaFuncSetAttribute(bd_attn_kernel,
                         cudaFuncAttributeMaxDynamicSharedMemorySize, smem_bytes);
    bd_attn_kernel<<<bh * TILES, 128, smem_bytes>>>(q, k, v, out);
}

// round 5
// speedup vs baseline: 2.8434x; 1.3171x over previous
#include <cuda_runtime.h>
#include <cuda_bf16.h>

// BlockDiagAttention: B=4,H=16,N=4128,D=64. fp32 in/out.
// R5: split-bf16 mma path + ldmatrix fragment loads (x4 / x4.trans),
// V row-major in smem (reuses Q buffers after GEMM1), 5 CTAs/SM.
#define NSEQ  4128
#define TILES 65
#define QSTR  36   // u32 per smem row (144 B): conflict-free for LDSM & uint4 STS

__device__ __forceinline__ void mma16816(float c[4], const unsigned a[4],
                                         const unsigned b[2]) {
    asm volatile(
        "mma.sync.aligned.m16n8k16.row.col.f32.bf16.bf16.f32 "
        "{%0,%1,%2,%3}, {%4,%5,%6,%7}, {%8,%9}, {%0,%1,%2,%3};"
        : "+f"(c[0]), "+f"(c[1]), "+f"(c[2]), "+f"(c[3])
        : "r"(a[0]), "r"(a[1]), "r"(a[2]), "r"(a[3]), "r"(b[0]), "r"(b[1]));
}

__device__ __forceinline__ void ldsm_x4(unsigned r[4], unsigned addr) {
    asm volatile("ldmatrix.sync.aligned.m8n8.x4.shared.b16 {%0,%1,%2,%3}, [%4];"
                 : "=r"(r[0]), "=r"(r[1]), "=r"(r[2]), "=r"(r[3]) : "r"(addr));
}

__device__ __forceinline__ void ldsm_x4_t(unsigned r[4], unsigned addr) {
    asm volatile("ldmatrix.sync.aligned.m8n8.x4.trans.shared.b16 {%0,%1,%2,%3}, [%4];"
                 : "=r"(r[0]), "=r"(r[1]), "=r"(r[2]), "=r"(r[3]) : "r"(addr));
}

__device__ __forceinline__ void split2(float x0, float x1, unsigned& h, unsigned& l) {
    __nv_bfloat162 hh = __floats2bfloat162_rn(x0, x1);
    float r0 = x0 - __bfloat162float(hh.x);
    float r1 = x1 - __bfloat162float(hh.y);
    __nv_bfloat162 ll = __floats2bfloat162_rn(r0, r1);
    h = *(unsigned*)&hh;
    l = *(unsigned*)&ll;
}

extern __shared__ unsigned smem_u32[];

__global__ __launch_bounds__(128, 5)
void bd_attn_kernel(const float* __restrict__ q, const float* __restrict__ k,
                    const float* __restrict__ v, float* __restrict__ out)
{
    unsigned* sQh = smem_u32;              // later: V hi (row-major)
    unsigned* sQl = smem_u32 + 64 * QSTR;  // later: V lo
    unsigned* sKh = smem_u32 + 2 * 64 * QSTR;
    unsigned* sKl = smem_u32 + 3 * 64 * QSTR;

    const int tid  = threadIdx.x;
    const int bh   = blockIdx.x / TILES;
    const int t_   = blockIdx.x % TILES;
    const int row0 = t_ * 64;
    const int nrows = min(64, NSEQ - row0);   // 64 or 32

    const size_t base = ((size_t)bh * NSEQ + row0) * 64;
    const float* qb = q + base;
    const float* kb = k + base;
    const float* vb = v + base;

    // ---- L2 prefetch of V (consumed after GEMM1)
    {
        const char* vp = (const char*)vb;
        int lines = (nrows * 64 * 4) >> 7;
        for (int l = tid; l < lines; l += 128)
            asm volatile("prefetch.global.L2 [%0];" :: "l"(vp + (size_t)l * 128));
    }

    // ---- Load Q,K -> smem split bf16 (row-major, uint4 stores)
#pragma unroll
    for (int p = 0; p < 4; ++p) {
        int i  = tid + 128 * p;
        int r  = i >> 3;
        int c8 = (i & 7) << 3;
        float4 f0 = make_float4(0.f,0.f,0.f,0.f), f1 = f0, g0 = f0, g1 = f0;
        if (r < nrows) {
            f0 = *(const float4*)(qb + r * 64 + c8);
            f1 = *(const float4*)(qb + r * 64 + c8 + 4);
            g0 = *(const float4*)(kb + r * 64 + c8);
            g1 = *(const float4*)(kb + r * 64 + c8 + 4);
        }
        unsigned h[4], l[4];
        split2(f0.x, f0.y, h[0], l[0]); split2(f0.z, f0.w, h[1], l[1]);
        split2(f1.x, f1.y, h[2], l[2]); split2(f1.z, f1.w, h[3], l[3]);
        *(uint4*)&sQh[r * QSTR + (c8 >> 1)] = make_uint4(h[0],h[1],h[2],h[3]);
        *(uint4*)&sQl[r * QSTR + (c8 >> 1)] = make_uint4(l[0],l[1],l[2],l[3]);
        split2(g0.x, g0.y, h[0], l[0]); split2(g0.z, g0.w, h[1], l[1]);
        split2(g1.x, g1.y, h[2], l[2]); split2(g1.z, g1.w, h[3], l[3]);
        *(uint4*)&sKh[r * QSTR + (c8 >> 1)] = make_uint4(h[0],h[1],h[2],h[3]);
        *(uint4*)&sKl[r * QSTR + (c8 >> 1)] = make_uint4(l[0],l[1],l[2],l[3]);
    }
    __syncthreads();

    const int lane = tid & 31;
    const int w    = tid >> 5;
    const int g    = lane >> 2;
    const int t    = lane & 3;
    const int i8   = lane >> 3;        // ldmatrix tile index 0..3

    const unsigned sQh_b = (unsigned)__cvta_generic_to_shared(sQh);
    const unsigned sQl_b = (unsigned)__cvta_generic_to_shared(sQl);
    const unsigned sKh_b = (unsigned)__cvta_generic_to_shared(sKh);
    const unsigned sKl_b = (unsigned)__cvta_generic_to_shared(sKl);

    // A frag lanes: tiles (m0,k0),(m0+8,k0),(m0,k0+8),(m0+8,k0+8)
    const int aRow = 16 * w + (i8 & 1) * 8 + (lane & 7);
    const unsigned aOff = aRow * 144 + (i8 >> 1) * 16;
    // GEMM1 B lanes: tiles (n0,k0),(n0,k0+8),(n0+8,k0),(n0+8,k0+8); n0=16*chp
    const unsigned bOff = ((i8 >> 1) * 8 + (lane & 7)) * 144 + (i8 & 1) * 16;
    // GEMM2 B lanes (trans): tiles (m0,d0),(m0+8,d0),(m0,d0+8),(m0+8,d0+8)
    const unsigned cOff = ((i8 & 1) * 8 + (lane & 7)) * 144 + (i8 >> 1) * 16;

    // ---- GEMM1: S = Q K^T  (hh + hl + lh)
    float acc[8][4];
#pragma unroll
    for (int ch = 0; ch < 8; ++ch)
#pragma unroll
        for (int j = 0; j < 4; ++j) acc[ch][j] = 0.f;

#pragma unroll
    for (int kk = 0; kk < 4; ++kk) {
        unsigned aH[4], aL[4];
        ldsm_x4(aH, sQh_b + aOff + kk * 32);
        ldsm_x4(aL, sQl_b + aOff + kk * 32);
#pragma unroll
        for (int chp = 0; chp < 4; ++chp) {
            unsigned bH[4], bL[4];
            ldsm_x4(bH, sKh_b + bOff + chp * 2304 + kk * 32);
            ldsm_x4(bL, sKl_b + bOff + chp * 2304 + kk * 32);
            mma16816(acc[2*chp],   aH, &bH[0]);
            mma16816(acc[2*chp],   aH, &bL[0]);
            mma16816(acc[2*chp],   aL, &bH[0]);
            mma16816(acc[2*chp+1], aH, &bH[2]);
            mma16816(acc[2*chp+1], aH, &bL[2]);
            mma16816(acc[2*chp+1], aL, &bH[2]);
        }
    }

    // ---- softmax in registers (rows g / g+8; cols 8ch+2t+(j&1))
    float mx0 = -1e30f, mx1 = -1e30f;
#pragma unroll
    for (int ch = 0; ch < 8; ++ch) {
#pragma unroll
        for (int j = 0; j < 4; ++j) {
            int col = 8 * ch + 2 * t + (j & 1);
            acc[ch][j] = (col < nrows) ? acc[ch][j] * 0.125f : -1e30f;
        }
        mx0 = fmaxf(mx0, fmaxf(acc[ch][0], acc[ch][1]));
        mx1 = fmaxf(mx1, fmaxf(acc[ch][2], acc[ch][3]));
    }
    mx0 = fmaxf(mx0, __shfl_xor_sync(0xffffffffu, mx0, 1));
    mx0 = fmaxf(mx0, __shfl_xor_sync(0xffffffffu, mx0, 2));
    mx1 = fmaxf(mx1, __shfl_xor_sync(0xffffffffu, mx1, 1));
    mx1 = fmaxf(mx1, __shfl_xor_sync(0xffffffffu, mx1, 2));

    float sum0 = 0.f, sum1 = 0.f;
#pragma unroll
    for (int ch = 0; ch < 8; ++ch) {
        acc[ch][0] = __expf(acc[ch][0] - mx0);
        acc[ch][1] = __expf(acc[ch][1] - mx0);
        acc[ch][2] = __expf(acc[ch][2] - mx1);
        acc[ch][3] = __expf(acc[ch][3] - mx1);
        sum0 += acc[ch][0] + acc[ch][1];
        sum1 += acc[ch][2] + acc[ch][3];
    }
    sum0 += __shfl_xor_sync(0xffffffffu, sum0, 1);
    sum0 += __shfl_xor_sync(0xffffffffu, sum0, 2);
    sum1 += __shfl_xor_sync(0xffffffffu, sum1, 1);
    sum1 += __shfl_xor_sync(0xffffffffu, sum1, 2);
    const float inv0 = __frcp_rn(sum0);
    const float inv1 = __frcp_rn(sum1);

    // ---- P fragments (GEMM1 C-layout == GEMM2 A-layout)
    unsigned pH[4][4], pL[4][4];
#pragma unroll
    for (int kk = 0; kk < 4; ++kk) {
        split2(acc[2*kk][0]   * inv0, acc[2*kk][1]   * inv0, pH[kk][0], pL[kk][0]);
        split2(acc[2*kk][2]   * inv1, acc[2*kk][3]   * inv1, pH[kk][1], pL[kk][1]);
        split2(acc[2*kk+1][0] * inv0, acc[2*kk+1][1] * inv0, pH[kk][2], pL[kk][2]);
        split2(acc[2*kk+1][2] * inv1, acc[2*kk+1][3] * inv1, pH[kk][3], pL[kk][3]);
    }

    __syncthreads();   // GEMM1 smem reads done; sQh/sQl become V hi/lo

    // ---- Load V -> smem split bf16, ROW-MAJOR (same path as Q/K)
#pragma unroll
    for (int p = 0; p < 4; ++p) {
        int i  = tid + 128 * p;
        int r  = i >> 3;
        int c8 = (i & 7) << 3;
        float4 f0 = make_float4(0.f,0.f,0.f,0.f), f1 = f0;
        if (r < nrows) {
            f0 = *(const float4*)(vb + r * 64 + c8);
            f1 = *(const float4*)(vb + r * 64 + c8 + 4);
        }
        unsigned h[4], l[4];
        split2(f0.x, f0.y, h[0], l[0]); split2(f0.z, f0.w, h[1], l[1]);
        split2(f1.x, f1.y, h[2], l[2]); split2(f1.z, f1.w, h[3], l[3]);
        *(uint4*)&sQh[r * QSTR + (c8 >> 1)] = make_uint4(h[0],h[1],h[2],h[3]);
        *(uint4*)&sQl[r * QSTR + (c8 >> 1)] = make_uint4(l[0],l[1],l[2],l[3]);
    }
    __syncthreads();

    // ---- GEMM2: O = P V  (B frags via ldmatrix.trans on row-major V)
#pragma unroll
    for (int ch = 0; ch < 8; ++ch)
#pragma unroll
        for (int j = 0; j < 4; ++j) acc[ch][j] = 0.f;

#pragma unroll
    for (int kk = 0; kk < 4; ++kk) {
#pragma unroll
        for (int chp = 0; chp < 4; ++chp) {
            unsigned vH[4], vL[4];
            ldsm_x4_t(vH, sQh_b + cOff + kk * 2304 + chp * 32);
            ldsm_x4_t(vL, sQl_b + cOff + kk * 2304 + chp * 32);
            mma16816(acc[2*chp],   pH[kk], &vH[0]);
            mma16816(acc[2*chp],   pH[kk], &vL[0]);
            mma16816(acc[2*chp],   pL[kk], &vH[0]);
            mma16816(acc[2*chp+1], pH[kk], &vH[2]);
            mma16816(acc[2*chp+1], pH[kk], &vL[2]);
            mma16816(acc[2*chp+1], pL[kk], &vH[2]);
        }
    }

    // ---- write O
    float* ob = out + base;
    const int r0 = 16 * w + g;
    const int r1 = r0 + 8;
#pragma unroll
    for (int ch = 0; ch < 8; ++ch) {
        int col = 8 * ch + 2 * t;
        if (r0 < nrows)
            *(float2*)(ob + r0 * 64 + col) = make_float2(acc[ch][0], acc[ch][1]);
        if (r1 < nrows)
            *(float2*)(ob + r1 * 64 + col) = make_float2(acc[ch][2], acc[ch][3]);
    }
}

extern "C" void kernel_launch(void* const* d_in, const int* in_sizes, int n_in,
                              void* d_out, int out_size) {
    const float* q = (const float*)d_in[0];
    const float* k = (const float*)d_in[1];
    const float* v = (const float*)d_in[2];
    float* out = (float*)d_out;

    const int bh = in_sizes[0] / (NSEQ * 64);                      // 64
    const int smem_bytes = 4 * 64 * QSTR * (int)sizeof(unsigned);  // 36864

    cudaFuncSetAttribute(bd_attn_kernel,
                         cudaFuncAttributeMaxDynamicSharedMemorySize, smem_bytes);
    bd_attn_kernel<<<bh * TILES, 128, smem_bytes>>>(q, k, v, out);
}